// round 13
// baseline (speedup 1.0000x reference)
#include <cuda_runtime.h>
#include <math.h>
#include <stdint.h>

// Problem dims
#define NB 256
#define NT 512
#define ND 64
#define NH 512
#define NC 64
#define DTF 0.1f

// Scan config: grid (32 h-tiles, 4 m-tiles) = 128 CTAs, 256 threads (2 teams x 128)
#define TPB 256
#define BM 64
#define BK 32
// smem: B [576][32] | A stages 2 teams x 3 x [32][128] | sred 128x8 u64
#define SMEM_B_FLOATS   (576 * 32)
#define SMEM_A_FLOATS   (2 * 3 * BK * 128)
#define SMEM_RED_BYTES  (128 * 8 * 8)
#define SMEM_BYTES      ((SMEM_B_FLOATS + SMEM_A_FLOATS) * 4 + SMEM_RED_BYTES)

// FC tiling
#define FBM 64

// Static scratch
__device__ float g_B[576 * 1024];             // [k][n], n=(h/2)*4+{z0,z1,v0,v1}
__device__ float g_xdup[NT * ND * 2 * NB];    // [t][d][2m]
__device__ float g_rdup[4 * NH * 2 * NB];     // 4-slot ring: [t%4][h][2m]
__device__ float g_fcT[NH * NC];
__device__ unsigned int g_flag[4 * 32];       // [by][bx] = steps completed
__device__ unsigned int g_cnt[4 * 32];        // [by*32] = sum of completed steps

// ---------------------------------------------------------------------------
__device__ __forceinline__ void fma2(unsigned long long &d,
                                     unsigned long long a,
                                     unsigned long long b) {
    asm("fma.rn.f32x2 %0, %1, %2, %0;" : "+l"(d) : "l"(a), "l"(b));
}
__device__ __forceinline__ unsigned long long add2(unsigned long long a,
                                                   unsigned long long b) {
    unsigned long long r;
    asm("add.rn.f32x2 %0, %1, %2;" : "=l"(r) : "l"(a), "l"(b));
    return r;
}
__device__ __forceinline__ float2 u2f(unsigned long long u) {
    float2 r;
    asm("mov.b64 {%0, %1}, %2;" : "=f"(r.x), "=f"(r.y) : "l"(u));
    return r;
}
__device__ __forceinline__ void cp16(uint32_t dst, const void* src) {
    asm volatile("cp.async.cg.shared.global [%0], [%1], 16;" :: "r"(dst), "l"(src));
}
#define CP_COMMIT() asm volatile("cp.async.commit_group;")
#define BAR_TEAM(id) asm volatile("bar.sync %0, 128;" :: "r"(id) : "memory")

// ---------------------------------------------------------------------------
__global__ void prep_kernel(const float* __restrict__ W,  const float* __restrict__ P,
                            const float* __restrict__ Kw, const float* __restrict__ Pz,
                            const float* __restrict__ fcw) {
    int idx = blockIdx.x * blockDim.x + threadIdx.x;
    if (idx < 128) { g_flag[idx] = 0u; g_cnt[idx] = 0u; }
    const int totalB = 576 * 1024;
    if (idx < totalB) {
        int k = idx >> 10;
        int n = idx & 1023;
        int h = ((n >> 2) << 1) | (n & 1);
        bool isv = (n & 2) != 0;
        float val;
        if (k < NH) {
            val = isv ? W[h * NH + k] : Kw[h * NH + k];
        } else {
            int d = k - NH;
            val = isv ? ((h < NH / 2) ? P[h * ND + d] : 0.0f)
                      : Pz[h * ND + d];
        }
        g_B[idx] = val;
    } else {
        int j = idx - totalB;
        if (j < NH * NC) {
            int k = j >> 6;
            int c = j & 63;
            g_fcT[j] = fcw[c * NH + k];
        }
    }
}

__global__ void __launch_bounds__(256)
prep_xdup(const float* __restrict__ x) {
    __shared__ float s[64][33];
    const int t  = blockIdx.x;
    const int m0 = blockIdx.y * 32;
    const int tid = threadIdx.x;
#pragma unroll
    for (int i = 0; i < 8; i++) {
        int idx = tid + i * 256;
        int ml = idx >> 6, d = idx & 63;
        s[d][ml] = x[((size_t)(m0 + ml) * NT + t) * ND + d];
    }
    __syncthreads();
#pragma unroll
    for (int i = 0; i < 8; i++) {
        int idx = tid + i * 256;
        int d = idx >> 5, ml = idx & 31;
        float v = s[d][ml];
        *(float2*)&g_xdup[((size_t)t * ND + d) * 512 + 2 * (m0 + ml)] = make_float2(v, v);
    }
}

// ---------------------------------------------------------------------------
// Persistent scan with fine-grained producer/consumer flags.
// ---------------------------------------------------------------------------
__global__ void __launch_bounds__(TPB)
scan_kernel(const float* __restrict__ bz_g,
            const float* __restrict__ bv_g,
            float* __restrict__ hid)
{
    extern __shared__ float smem[];
    float* sBf = smem;                                   // [576][32]
    float* sA  = smem + SMEM_B_FLOATS;                   // 2 teams x 3 x [32][128]
    unsigned long long* sred =
        (unsigned long long*)(smem + SMEM_B_FLOATS + SMEM_A_FLOATS); // [128][8]

    const int tid  = threadIdx.x;
    const int team = tid >> 7;          // 0 or 1
    const int ttid = tid & 127;
    const int bx   = blockIdx.x;        // h-tile 0..31
    const int by   = blockIdx.y;        // m-tile 0..3
    const int m0   = by * BM;
    const int tx   = ttid & 7;          // h-pair 0..7
    const int ty   = ttid >> 3;         // m-quad 0..15

    unsigned int* cntp  = &g_cnt[by * 32];
    unsigned int* flagp = &g_flag[by * 32 + bx];

    // ---- load B slice once ----
#pragma unroll
    for (int r = 0; r < 18; r++) {
        int i = tid + r * TPB;
        int row = i >> 3, c = (i & 7) << 2;
        uint32_t dst = (uint32_t)__cvta_generic_to_shared(&sBf[row * 32 + c]);
        cp16(dst, g_B + (size_t)row * 1024 + bx * 32 + c);
    }
    CP_COMMIT();
    asm volatile("cp.async.wait_group 0;");
    __syncthreads();

    const int h2 = bx * 8 + tx;
    const int hg = h2 * 2;
    const float2 bz = *(const float2*)&bz_g[hg];
    const float2 bv = *(const float2*)&bv_g[hg];

    float* sAteam = sA + team * (3 * BK * 128);
    const int barid = 1 + team;

    // v-state (team 0 threads own it): 4 m x (h0,h1)
    float2 vs0 = {0,0}, vs1 = {0,0}, vs2 = {0,0}, vs3 = {0,0};

    auto issueChunk = [&](int stg, const float* gbase) {
#pragma unroll
        for (int r = 0; r < 8; r++) {
            int id = ttid + r * 128;
            int kk = id >> 5, c = (id & 31) << 2;
            uint32_t dst = (uint32_t)__cvta_generic_to_shared(
                &sAteam[(stg * BK + kk) * 128 + c]);
            cp16(dst, gbase + (size_t)kk * 512 + c);
        }
        CP_COMMIT();
    };

    unsigned long long az0, az1, az2, az3, av0, av1, av2, av3;

    auto computeChunk = [&](int stg, int kbase) {
        const float* pa = sAteam + (stg * BK) * 128 + ty * 8;
        const float* pb = sBf + kbase * 32 + tx * 4;
        ulonglong2 a0 = *(const ulonglong2*)(pa);
        ulonglong2 a1 = *(const ulonglong2*)(pa + 4);
        ulonglong2 b  = *(const ulonglong2*)(pb);
#pragma unroll
        for (int kk = 0; kk < BK; ++kk) {
            ulonglong2 na0, na1, nb;
            if (kk < BK - 1) {
                na0 = *(const ulonglong2*)(pa + (kk + 1) * 128);
                na1 = *(const ulonglong2*)(pa + (kk + 1) * 128 + 4);
                nb  = *(const ulonglong2*)(pb + (kk + 1) * 32);
            }
            fma2(az0, a0.x, b.x); fma2(av0, a0.x, b.y);
            fma2(az1, a0.y, b.x); fma2(av1, a0.y, b.y);
            fma2(az2, a1.x, b.x); fma2(av2, a1.x, b.y);
            fma2(az3, a1.y, b.x); fma2(av3, a1.y, b.y);
            if (kk < BK - 1) { a0 = na0; a1 = na1; b = nb; }
        }
    };

    // chunk 0 = x (d in [32*team, 32*team+32)); chunks 1..8 = recurrent
    const size_t xoff = (size_t)32 * team * 512 + 2 * m0;
    const size_t roff = (size_t)256 * team * 512 + 2 * m0;
    const int kb_x = 512 + 32 * team;
    const int kb_r = 256 * team;
    const int fbase = by * 32 + 16 * team;   // producer flag base for this team

    // prologue: x chunk for t=0
    issueChunk(0, g_xdup + xoff);

#pragma unroll 1
    for (int t = 0; t < NT; ++t) {
        az0 = az1 = az2 = az3 = 0ull;
        av0 = av1 = av2 = av3 = 0ull;

        // wait (fine-grained) for the 2 producers of recurrent chunk n
        auto pollFlag = [&](int n) {
            const unsigned int* f = &g_flag[fbase + 2 * (n - 1)];
            unsigned int v;
            do {
                asm volatile("ld.acquire.gpu.global.u32 %0, [%1];"
                             : "=r"(v) : "l"(f));
            } while (v < (unsigned)t);
            do {
                asm volatile("ld.acquire.gpu.global.u32 %0, [%1];"
                             : "=r"(v) : "l"(f + 1));
            } while (v < (unsigned)t);
        };

        if (t == 0) {
            asm volatile("cp.async.wait_group 0;");
            BAR_TEAM(barid);
            computeChunk(0, kb_x);
        } else {
            const float* rbase = g_rdup + (size_t)((t - 1) & 3) * (NH * 512) + roff;
            pollFlag(1);
            issueChunk(1, rbase);                     // chunk 1
#pragma unroll 1
            for (int c = 0; c <= 8; ++c) {
                if (c < 8) { asm volatile("cp.async.wait_group 1;"); }
                else       { asm volatile("cp.async.wait_group 0;"); }
                BAR_TEAM(barid);
                if (c + 2 <= 8) {
                    pollFlag(c + 2);
                    issueChunk((c + 2) % 3, rbase + (size_t)(c + 1) * BK * 512);
                }
                computeChunk(c % 3, (c == 0) ? kb_x : (kb_r + (c - 1) * BK));
            }
        }

        // ---- cross-team reduction ----
        if (team == 1) {
            unsigned long long* d = &sred[ttid * 8];
            *(ulonglong2*)(d)     = make_ulonglong2(az0, av0);
            *(ulonglong2*)(d + 2) = make_ulonglong2(az1, av1);
            *(ulonglong2*)(d + 4) = make_ulonglong2(az2, av2);
            *(ulonglong2*)(d + 6) = make_ulonglong2(az3, av3);
        }
        __syncthreads();

        if (team == 0) {
            const unsigned long long* d = &sred[ttid * 8];
            ulonglong2 q0 = *(const ulonglong2*)(d);
            ulonglong2 q1 = *(const ulonglong2*)(d + 2);
            ulonglong2 q2 = *(const ulonglong2*)(d + 4);
            ulonglong2 q3 = *(const ulonglong2*)(d + 6);
            az0 = add2(az0, q0.x); av0 = add2(av0, q0.y);
            az1 = add2(az1, q1.x); av1 = add2(av1, q1.y);
            az2 = add2(az2, q2.x); av2 = add2(av2, q2.y);
            az3 = add2(az3, q3.x); av3 = add2(av3, q3.y);

            const int mA = m0 + 4 * ty;
            float2 z, v;

            z = u2f(az0); v = u2f(av0);
            {
                float s0 = 1.0f / (1.0f + __expf(-(z.x + bz.x)));
                float s1 = 1.0f / (1.0f + __expf(-(z.y + bz.y)));
                vs0.x = (1.0f - s0) * vs0.x + DTF * (v.x + bv.x);
                vs0.y = (1.0f - s1) * vs0.y + DTF * (v.y + bv.y);
            }
            z = u2f(az1); v = u2f(av1);
            {
                float s0 = 1.0f / (1.0f + __expf(-(z.x + bz.x)));
                float s1 = 1.0f / (1.0f + __expf(-(z.y + bz.y)));
                vs1.x = (1.0f - s0) * vs1.x + DTF * (v.x + bv.x);
                vs1.y = (1.0f - s1) * vs1.y + DTF * (v.y + bv.y);
            }
            z = u2f(az2); v = u2f(av2);
            {
                float s0 = 1.0f / (1.0f + __expf(-(z.x + bz.x)));
                float s1 = 1.0f / (1.0f + __expf(-(z.y + bz.y)));
                vs2.x = (1.0f - s0) * vs2.x + DTF * (v.x + bv.x);
                vs2.y = (1.0f - s1) * vs2.y + DTF * (v.y + bv.y);
            }
            z = u2f(az3); v = u2f(av3);
            {
                float s0 = 1.0f / (1.0f + __expf(-(z.x + bz.x)));
                float s1 = 1.0f / (1.0f + __expf(-(z.y + bz.y)));
                vs3.x = (1.0f - s0) * vs3.x + DTF * (v.x + bv.x);
                vs3.y = (1.0f - s1) * vs3.y + DTF * (v.y + bv.y);
            }

            // slot-reuse slack check: slot t%4 was read during step t-3;
            // require all group CTAs to have completed step t-3.
            if (t >= 3) {
                unsigned int need = 32u * (unsigned)(t - 2);
                unsigned int vv;
                do {
                    asm volatile("ld.acquire.gpu.global.u32 %0, [%1];"
                                 : "=r"(vv) : "l"(cntp));
                } while (vv < need);
            }

            *(float2*)&hid[((size_t)(mA + 0) * NT + t) * NH + hg] = vs0;
            *(float2*)&hid[((size_t)(mA + 1) * NT + t) * NH + hg] = vs1;
            *(float2*)&hid[((size_t)(mA + 2) * NT + t) * NH + hg] = vs2;
            *(float2*)&hid[((size_t)(mA + 3) * NT + t) * NH + hg] = vs3;

            const float r0x = fmaxf(vs0.x, 0.0f), r0y = fmaxf(vs0.y, 0.0f);
            const float r1x = fmaxf(vs1.x, 0.0f), r1y = fmaxf(vs1.y, 0.0f);
            const float r2x = fmaxf(vs2.x, 0.0f), r2y = fmaxf(vs2.y, 0.0f);
            const float r3x = fmaxf(vs3.x, 0.0f), r3y = fmaxf(vs3.y, 0.0f);

            float* rd = g_rdup + (size_t)(t & 3) * (NH * 512);
            float* sp0 = &rd[(size_t)hg * 512 + 2 * mA];
            ((float4*)sp0)[0] = make_float4(r0x, r0x, r1x, r1x);
            ((float4*)sp0)[1] = make_float4(r2x, r2x, r3x, r3x);
            float* sp1 = &rd[(size_t)(hg + 1) * 512 + 2 * mA];
            ((float4*)sp1)[0] = make_float4(r0y, r0y, r1y, r1y);
            ((float4*)sp1)[1] = make_float4(r2y, r2y, r3y, r3y);

            BAR_TEAM(barid);
            if (tid == 0) {
                asm volatile("st.release.gpu.global.u32 [%0], %1;"
                             :: "l"(flagp), "r"((unsigned)(t + 1)) : "memory");
                asm volatile("red.release.gpu.global.add.u32 [%0], %1;"
                             :: "l"(cntp), "r"(1u) : "memory");
            }
        }

        // prefetch x chunk for t+1 (state-independent)
        if (t + 1 < NT)
            issueChunk(0, g_xdup + (size_t)(t + 1) * (ND * 512) + xoff);
    }
}

// ---------------------------------------------------------------------------
// FC (unchanged)
// ---------------------------------------------------------------------------
__global__ void __launch_bounds__(128)
fc_kernel(const float* __restrict__ hid,
          const float* __restrict__ fcb,
          float* __restrict__ out)
{
    __shared__ __align__(16) float fA[2][16][2 * FBM];
    __shared__ __align__(16) float fB[2][16][NC];

    const int tid = threadIdx.x;
    const int m0 = blockIdx.x * FBM;
    const int tx = tid & 7;
    const int ty = tid >> 3;
    const int c0 = tx * 8;

    const int a_m = tid >> 1;
    const int a_k = (tid & 1) * 8;
    const int b_k = tid >> 3;
    const int b_q = (tid & 7) * 8;

    unsigned long long acc[4][4];
#pragma unroll
    for (int i = 0; i < 4; i++)
#pragma unroll
        for (int j = 0; j < 4; j++) acc[i][j] = 0ull;

    auto loadA = [&](int it, float4 &v0, float4 &v1) {
        const float* src = hid + (size_t)(m0 + a_m) * NH + it * 16 + a_k;
        v0 = ((const float4*)src)[0];
        v1 = ((const float4*)src)[1];
    };
    auto loadB = [&](int it, float4 &v0, float4 &v1) {
        const float* src = g_fcT + (size_t)(it * 16 + b_k) * NC + b_q;
        v0 = ((const float4*)src)[0];
        v1 = ((const float4*)src)[1];
    };
    auto stsA = [&](int buf, const float4 &v0, const float4 &v1) {
#pragma unroll
        for (int i = 0; i < 4; i++) {
            float a = (&v0.x)[i];
            *(float2*)&fA[buf][a_k + i][2 * a_m] = make_float2(a, a);
        }
#pragma unroll
        for (int i = 0; i < 4; i++) {
            float a = (&v1.x)[i];
            *(float2*)&fA[buf][a_k + 4 + i][2 * a_m] = make_float2(a, a);
        }
    };
    auto stsB = [&](int buf, const float4 &v0, const float4 &v1) {
        *(float4*)&fB[buf][b_k][b_q]     = v0;
        *(float4*)&fB[buf][b_k][b_q + 4] = v1;
    };

    float4 rA0, rA1, rB0, rB1;
    loadA(0, rA0, rA1); loadB(0, rB0, rB1);
    stsA(0, rA0, rA1); stsB(0, rB0, rB1);
    __syncthreads();

    int cur = 0;
    const int FNITER = NH / 16;
    for (int it = 0; it < FNITER; ++it) {
        const bool more = (it + 1) < FNITER;
        if (more) { loadA(it + 1, rA0, rA1); loadB(it + 1, rB0, rB1); }
#pragma unroll
        for (int kl = 0; kl < 16; ++kl) {
            const ulonglong2 aa0 = *(const ulonglong2*)&fA[cur][kl][8 * ty];
            const ulonglong2 aa1 = *(const ulonglong2*)&fA[cur][kl][8 * ty + 4];
            const ulonglong2 bb0 = *(const ulonglong2*)&fB[cur][kl][c0];
            const ulonglong2 bb1 = *(const ulonglong2*)&fB[cur][kl][c0 + 4];
            fma2(acc[0][0], aa0.x, bb0.x); fma2(acc[0][1], aa0.x, bb0.y);
            fma2(acc[0][2], aa0.x, bb1.x); fma2(acc[0][3], aa0.x, bb1.y);
            fma2(acc[1][0], aa0.y, bb0.x); fma2(acc[1][1], aa0.y, bb0.y);
            fma2(acc[1][2], aa0.y, bb1.x); fma2(acc[1][3], aa0.y, bb1.y);
            fma2(acc[2][0], aa1.x, bb0.x); fma2(acc[2][1], aa1.x, bb0.y);
            fma2(acc[2][2], aa1.x, bb1.x); fma2(acc[2][3], aa1.x, bb1.y);
            fma2(acc[3][0], aa1.y, bb0.x); fma2(acc[3][1], aa1.y, bb0.y);
            fma2(acc[3][2], aa1.y, bb1.x); fma2(acc[3][3], aa1.y, bb1.y);
        }
        if (more) { stsA(cur ^ 1, rA0, rA1); stsB(cur ^ 1, rB0, rB1); }
        __syncthreads();
        cur ^= 1;
    }

    const float4 fb0 = *(const float4*)&fcb[c0];
    const float4 fb1 = *(const float4*)&fcb[c0 + 4];
#pragma unroll
    for (int i = 0; i < 4; i++) {
        const int m = m0 + 4 * ty + i;
        const float2 p0 = u2f(acc[i][0]);
        const float2 p1 = u2f(acc[i][1]);
        const float2 p2 = u2f(acc[i][2]);
        const float2 p3 = u2f(acc[i][3]);
        float4 o0 = make_float4(p0.x + fb0.x, p0.y + fb0.y, p1.x + fb0.z, p1.y + fb0.w);
        float4 o1 = make_float4(p2.x + fb1.x, p2.y + fb1.y, p3.x + fb1.z, p3.y + fb1.w);
        float* dst = out + (size_t)m * NC + c0;
        ((float4*)dst)[0] = o0;
        ((float4*)dst)[1] = o1;
    }
}

// ---------------------------------------------------------------------------
extern "C" void kernel_launch(void* const* d_in, const int* in_sizes, int n_in,
                              void* d_out, int out_size)
{
    const float* x   = (const float*)d_in[0];
    const float* W   = (const float*)d_in[1];
    const float* P   = (const float*)d_in[2];
    const float* b_v = (const float*)d_in[3];
    const float* b_z = (const float*)d_in[4];
    const float* Kw  = (const float*)d_in[5];
    const float* Pz  = (const float*)d_in[6];
    const float* fcw = (const float*)d_in[7];
    const float* fcb = (const float*)d_in[8];

    float* out = (float*)d_out;
    float* hid = out + (size_t)NB * NT * NC;

    (void)in_sizes; (void)n_in; (void)out_size;

    static int smem_set = 0;
    if (!smem_set) {
        cudaFuncSetAttribute(scan_kernel,
                             cudaFuncAttributeMaxDynamicSharedMemorySize, SMEM_BYTES);
        smem_set = 1;
    }

    prep_kernel<<<(576 * 1024 + NH * NC + 255) / 256, 256>>>(W, P, Kw, Pz, fcw);
    prep_xdup<<<dim3(NT, NB / 32), 256>>>(x);

    dim3 sgrid(32, 4);   // 128 CTAs — one wave, persistent
    scan_kernel<<<sgrid, TPB, SMEM_BYTES>>>(b_z, b_v, hid);

    fc_kernel<<<(NB * NT) / FBM, 128>>>(hid, fcb, out);
}

// round 14
// speedup vs baseline: 1.1581x; 1.1581x over previous
#include <cuda_runtime.h>
#include <math.h>
#include <stdint.h>

// Problem dims
#define NB 256
#define NT 512
#define ND 64
#define NH 512
#define NC 64
#define DTF 0.1f

// Scan config: grid (32 h-tiles, 4 m-tiles) = 128 CTAs, 256 threads (2 teams x 128)
#define TPB 256
#define BM 64
#define BK 32
// smem: B [576][32] | A stages 2 teams x 3 x [32][128] | sred 128x8 u64
#define SMEM_B_FLOATS   (576 * 32)
#define SMEM_A_FLOATS   (2 * 3 * BK * 128)
#define SMEM_RED_BYTES  (128 * 8 * 8)
#define SMEM_BYTES      ((SMEM_B_FLOATS + SMEM_A_FLOATS) * 4 + SMEM_RED_BYTES)

// FC tiling
#define FBM 64

// Static scratch
__device__ float g_B[576 * 1024];             // [k][n], n=(h/2)*4+{z0,z1,v0,v1}
__device__ float g_xdup[NT * ND * 2 * NB];    // [t][d][2m]
__device__ float g_rdup[4 * NH * 2 * NB];     // 4-slot ring: [t%4][h][2m]
__device__ float g_fcT[NH * NC];
__device__ unsigned int g_flag[4 * 32];       // [by][bx] = steps completed
__device__ unsigned int g_cnt[4 * 32];        // [by*32] = group sum of steps

// ---------------------------------------------------------------------------
__device__ __forceinline__ void fma2(unsigned long long &d,
                                     unsigned long long a,
                                     unsigned long long b) {
    asm("fma.rn.f32x2 %0, %1, %2, %0;" : "+l"(d) : "l"(a), "l"(b));
}
__device__ __forceinline__ unsigned long long add2(unsigned long long a,
                                                   unsigned long long b) {
    unsigned long long r;
    asm("add.rn.f32x2 %0, %1, %2;" : "=l"(r) : "l"(a), "l"(b));
    return r;
}
__device__ __forceinline__ float2 u2f(unsigned long long u) {
    float2 r;
    asm("mov.b64 {%0, %1}, %2;" : "=f"(r.x), "=f"(r.y) : "l"(u));
    return r;
}
__device__ __forceinline__ void cp16(uint32_t dst, const void* src) {
    asm volatile("cp.async.cg.shared.global [%0], [%1], 16;" :: "r"(dst), "l"(src));
}
#define CP_COMMIT() asm volatile("cp.async.commit_group;")
#define BAR_TEAM(id) asm volatile("bar.sync %0, 128;" :: "r"(id) : "memory")

// ---------------------------------------------------------------------------
__global__ void prep_kernel(const float* __restrict__ W,  const float* __restrict__ P,
                            const float* __restrict__ Kw, const float* __restrict__ Pz,
                            const float* __restrict__ fcw) {
    int idx = blockIdx.x * blockDim.x + threadIdx.x;
    if (idx < 128) { g_flag[idx] = 0u; g_cnt[idx] = 0u; }
    const int totalB = 576 * 1024;
    if (idx < totalB) {
        int k = idx >> 10;
        int n = idx & 1023;
        int h = ((n >> 2) << 1) | (n & 1);
        bool isv = (n & 2) != 0;
        float val;
        if (k < NH) {
            val = isv ? W[h * NH + k] : Kw[h * NH + k];
        } else {
            int d = k - NH;
            val = isv ? ((h < NH / 2) ? P[h * ND + d] : 0.0f)
                      : Pz[h * ND + d];
        }
        g_B[idx] = val;
    } else {
        int j = idx - totalB;
        if (j < NH * NC) {
            int k = j >> 6;
            int c = j & 63;
            g_fcT[j] = fcw[c * NH + k];
        }
    }
}

__global__ void __launch_bounds__(256)
prep_xdup(const float* __restrict__ x) {
    __shared__ float s[64][33];
    const int t  = blockIdx.x;
    const int m0 = blockIdx.y * 32;
    const int tid = threadIdx.x;
#pragma unroll
    for (int i = 0; i < 8; i++) {
        int idx = tid + i * 256;
        int ml = idx >> 6, d = idx & 63;
        s[d][ml] = x[((size_t)(m0 + ml) * NT + t) * ND + d];
    }
    __syncthreads();
#pragma unroll
    for (int i = 0; i < 8; i++) {
        int idx = tid + i * 256;
        int d = idx >> 5, ml = idx & 31;
        float v = s[d][ml];
        *(float2*)&g_xdup[((size_t)t * ND + d) * 512 + 2 * (m0 + ml)] = make_float2(v, v);
    }
}

// ---------------------------------------------------------------------------
// Persistent scan: fine-grained producer->consumer flags, SINGLE-thread polls
// broadcast by the per-chunk team barrier.
// ---------------------------------------------------------------------------
__global__ void __launch_bounds__(TPB)
scan_kernel(const float* __restrict__ bz_g,
            const float* __restrict__ bv_g,
            float* __restrict__ hid)
{
    extern __shared__ float smem[];
    float* sBf = smem;                                   // [576][32]
    float* sA  = smem + SMEM_B_FLOATS;                   // 2 teams x 3 x [32][128]
    unsigned long long* sred =
        (unsigned long long*)(smem + SMEM_B_FLOATS + SMEM_A_FLOATS); // [128][8]

    const int tid  = threadIdx.x;
    const int team = tid >> 7;          // 0 or 1
    const int ttid = tid & 127;
    const int bx   = blockIdx.x;        // h-tile 0..31
    const int by   = blockIdx.y;        // m-tile 0..3
    const int m0   = by * BM;
    const int tx   = ttid & 7;          // h-pair 0..7
    const int ty   = ttid >> 3;         // m-quad 0..15

    unsigned int* cntp  = &g_cnt[by * 32];
    unsigned int* flagp = &g_flag[by * 32 + bx];

    // ---- load B slice once ----
#pragma unroll
    for (int r = 0; r < 18; r++) {
        int i = tid + r * TPB;
        int row = i >> 3, c = (i & 7) << 2;
        uint32_t dst = (uint32_t)__cvta_generic_to_shared(&sBf[row * 32 + c]);
        cp16(dst, g_B + (size_t)row * 1024 + bx * 32 + c);
    }
    CP_COMMIT();
    asm volatile("cp.async.wait_group 0;");
    __syncthreads();

    const int h2 = bx * 8 + tx;
    const int hg = h2 * 2;
    const float2 bz = *(const float2*)&bz_g[hg];
    const float2 bv = *(const float2*)&bv_g[hg];

    float* sAteam = sA + team * (3 * BK * 128);
    const int barid = 1 + team;

    // v-state (team 0 threads own it): 4 m x (h0,h1)
    float2 vs0 = {0,0}, vs1 = {0,0}, vs2 = {0,0}, vs3 = {0,0};

    auto issueChunk = [&](int stg, const float* gbase) {
#pragma unroll
        for (int r = 0; r < 8; r++) {
            int id = ttid + r * 128;
            int kk = id >> 5, c = (id & 31) << 2;
            uint32_t dst = (uint32_t)__cvta_generic_to_shared(
                &sAteam[(stg * BK + kk) * 128 + c]);
            cp16(dst, gbase + (size_t)kk * 512 + c);
        }
        CP_COMMIT();
    };

    unsigned long long az0, az1, az2, az3, av0, av1, av2, av3;

    auto computeChunk = [&](int stg, int kbase) {
        const float* pa = sAteam + (stg * BK) * 128 + ty * 8;
        const float* pb = sBf + kbase * 32 + tx * 4;
        ulonglong2 a0 = *(const ulonglong2*)(pa);
        ulonglong2 a1 = *(const ulonglong2*)(pa + 4);
        ulonglong2 b  = *(const ulonglong2*)(pb);
#pragma unroll
        for (int kk = 0; kk < BK; ++kk) {
            ulonglong2 na0, na1, nb;
            if (kk < BK - 1) {
                na0 = *(const ulonglong2*)(pa + (kk + 1) * 128);
                na1 = *(const ulonglong2*)(pa + (kk + 1) * 128 + 4);
                nb  = *(const ulonglong2*)(pb + (kk + 1) * 32);
            }
            fma2(az0, a0.x, b.x); fma2(av0, a0.x, b.y);
            fma2(az1, a0.y, b.x); fma2(av1, a0.y, b.y);
            fma2(az2, a1.x, b.x); fma2(av2, a1.x, b.y);
            fma2(az3, a1.y, b.x); fma2(av3, a1.y, b.y);
            if (kk < BK - 1) { a0 = na0; a1 = na1; b = nb; }
        }
    };

    // chunk 0 = x (d in [32*team, 32*team+32)); chunks 1..8 = recurrent
    const size_t xoff = (size_t)32 * team * 512 + 2 * m0;
    const size_t roff = (size_t)256 * team * 512 + 2 * m0;
    const int kb_x = 512 + 32 * team;
    const int kb_r = 256 * team;
    const int fbase = by * 32 + 16 * team;   // producer flag base for this team

    // prologue: x chunk for t=0
    issueChunk(0, g_xdup + xoff);

#pragma unroll 1
    for (int t = 0; t < NT; ++t) {
        az0 = az1 = az2 = az3 = 0ull;
        av0 = av1 = av2 = av3 = 0ull;

        // single-thread poll of the 2 producers of recurrent chunk n
        auto pollOne = [&](int n) {
            const unsigned int* f = &g_flag[fbase + 2 * (n - 1)];
            unsigned int v;
            do {
                asm volatile("ld.acquire.gpu.global.u32 %0, [%1];"
                             : "=r"(v) : "l"(f));
            } while (v < (unsigned)t);
            do {
                asm volatile("ld.acquire.gpu.global.u32 %0, [%1];"
                             : "=r"(v) : "l"(f + 1));
            } while (v < (unsigned)t);
        };

        if (t == 0) {
            asm volatile("cp.async.wait_group 0;");
            BAR_TEAM(barid);
            computeChunk(0, kb_x);
        } else {
            const float* rbase = g_rdup + (size_t)((t - 1) & 3) * (NH * 512) + roff;
            // poll chunks 1 and 2 (two different warps), broadcast via BAR
            if (ttid == 0)  pollOne(1);
            if (ttid == 32) pollOne(2);
            BAR_TEAM(barid);
            issueChunk(1, rbase);                     // chunk 1
#pragma unroll 1
            for (int c = 0; c <= 8; ++c) {
                if (c < 8) { asm volatile("cp.async.wait_group 1;"); }
                else       { asm volatile("cp.async.wait_group 0;"); }
                BAR_TEAM(barid);
                // poll for chunk c+3 (one rotating thread); BAR at iter c+1
                // broadcasts before that chunk is issued
                if (c + 3 <= 8 && ttid == (((c + 1) & 3) << 5))
                    pollOne(c + 3);
                if (c + 2 <= 8)
                    issueChunk((c + 2) % 3, rbase + (size_t)(c + 1) * BK * 512);
                computeChunk(c % 3, (c == 0) ? kb_x : (kb_r + (c - 1) * BK));
            }
        }

        // ---- cross-team reduction (two syncs: write-race protection) ----
        __syncthreads();
        if (team == 1) {
            unsigned long long* d = &sred[ttid * 8];
            *(ulonglong2*)(d)     = make_ulonglong2(az0, av0);
            *(ulonglong2*)(d + 2) = make_ulonglong2(az1, av1);
            *(ulonglong2*)(d + 4) = make_ulonglong2(az2, av2);
            *(ulonglong2*)(d + 6) = make_ulonglong2(az3, av3);
        }
        __syncthreads();

        if (team == 0) {
            const unsigned long long* d = &sred[ttid * 8];
            ulonglong2 q0 = *(const ulonglong2*)(d);
            ulonglong2 q1 = *(const ulonglong2*)(d + 2);
            ulonglong2 q2 = *(const ulonglong2*)(d + 4);
            ulonglong2 q3 = *(const ulonglong2*)(d + 6);
            az0 = add2(az0, q0.x); av0 = add2(av0, q0.y);
            az1 = add2(az1, q1.x); av1 = add2(av1, q1.y);
            az2 = add2(az2, q2.x); av2 = add2(av2, q2.y);
            az3 = add2(az3, q3.x); av3 = add2(av3, q3.y);

            const int mA = m0 + 4 * ty;
            float2 z, v;

            z = u2f(az0); v = u2f(av0);
            {
                float s0 = 1.0f / (1.0f + __expf(-(z.x + bz.x)));
                float s1 = 1.0f / (1.0f + __expf(-(z.y + bz.y)));
                vs0.x = (1.0f - s0) * vs0.x + DTF * (v.x + bv.x);
                vs0.y = (1.0f - s1) * vs0.y + DTF * (v.y + bv.y);
            }
            z = u2f(az1); v = u2f(av1);
            {
                float s0 = 1.0f / (1.0f + __expf(-(z.x + bz.x)));
                float s1 = 1.0f / (1.0f + __expf(-(z.y + bz.y)));
                vs1.x = (1.0f - s0) * vs1.x + DTF * (v.x + bv.x);
                vs1.y = (1.0f - s1) * vs1.y + DTF * (v.y + bv.y);
            }
            z = u2f(az2); v = u2f(av2);
            {
                float s0 = 1.0f / (1.0f + __expf(-(z.x + bz.x)));
                float s1 = 1.0f / (1.0f + __expf(-(z.y + bz.y)));
                vs2.x = (1.0f - s0) * vs2.x + DTF * (v.x + bv.x);
                vs2.y = (1.0f - s1) * vs2.y + DTF * (v.y + bv.y);
            }
            z = u2f(az3); v = u2f(av3);
            {
                float s0 = 1.0f / (1.0f + __expf(-(z.x + bz.x)));
                float s1 = 1.0f / (1.0f + __expf(-(z.y + bz.y)));
                vs3.x = (1.0f - s0) * vs3.x + DTF * (v.x + bv.x);
                vs3.y = (1.0f - s1) * vs3.y + DTF * (v.y + bv.y);
            }

            // slot-reuse slack: before overwriting ring slot t%4, require all
            // group CTAs past step t-3. Single thread polls; BAR broadcasts.
            if (t >= 3 && tid == 0) {
                unsigned int need = 32u * (unsigned)(t - 2);
                unsigned int vv;
                do {
                    asm volatile("ld.acquire.gpu.global.u32 %0, [%1];"
                                 : "=r"(vv) : "l"(cntp));
                } while (vv < need);
            }
            BAR_TEAM(barid);

            *(float2*)&hid[((size_t)(mA + 0) * NT + t) * NH + hg] = vs0;
            *(float2*)&hid[((size_t)(mA + 1) * NT + t) * NH + hg] = vs1;
            *(float2*)&hid[((size_t)(mA + 2) * NT + t) * NH + hg] = vs2;
            *(float2*)&hid[((size_t)(mA + 3) * NT + t) * NH + hg] = vs3;

            const float r0x = fmaxf(vs0.x, 0.0f), r0y = fmaxf(vs0.y, 0.0f);
            const float r1x = fmaxf(vs1.x, 0.0f), r1y = fmaxf(vs1.y, 0.0f);
            const float r2x = fmaxf(vs2.x, 0.0f), r2y = fmaxf(vs2.y, 0.0f);
            const float r3x = fmaxf(vs3.x, 0.0f), r3y = fmaxf(vs3.y, 0.0f);

            float* rd = g_rdup + (size_t)(t & 3) * (NH * 512);
            float* sp0 = &rd[(size_t)hg * 512 + 2 * mA];
            ((float4*)sp0)[0] = make_float4(r0x, r0x, r1x, r1x);
            ((float4*)sp0)[1] = make_float4(r2x, r2x, r3x, r3x);
            float* sp1 = &rd[(size_t)(hg + 1) * 512 + 2 * mA];
            ((float4*)sp1)[0] = make_float4(r0y, r0y, r1y, r1y);
            ((float4*)sp1)[1] = make_float4(r2y, r2y, r3y, r3y);

            BAR_TEAM(barid);
            if (tid == 0) {
                asm volatile("st.release.gpu.global.u32 [%0], %1;"
                             :: "l"(flagp), "r"((unsigned)(t + 1)) : "memory");
                asm volatile("red.release.gpu.global.add.u32 [%0], %1;"
                             :: "l"(cntp), "r"(1u) : "memory");
            }
        }

        // prefetch x chunk for t+1 (state-independent)
        if (t + 1 < NT)
            issueChunk(0, g_xdup + (size_t)(t + 1) * (ND * 512) + xoff);
    }
}

// ---------------------------------------------------------------------------
// FC (unchanged)
// ---------------------------------------------------------------------------
__global__ void __launch_bounds__(128)
fc_kernel(const float* __restrict__ hid,
          const float* __restrict__ fcb,
          float* __restrict__ out)
{
    __shared__ __align__(16) float fA[2][16][2 * FBM];
    __shared__ __align__(16) float fB[2][16][NC];

    const int tid = threadIdx.x;
    const int m0 = blockIdx.x * FBM;
    const int tx = tid & 7;
    const int ty = tid >> 3;
    const int c0 = tx * 8;

    const int a_m = tid >> 1;
    const int a_k = (tid & 1) * 8;
    const int b_k = tid >> 3;
    const int b_q = (tid & 7) * 8;

    unsigned long long acc[4][4];
#pragma unroll
    for (int i = 0; i < 4; i++)
#pragma unroll
        for (int j = 0; j < 4; j++) acc[i][j] = 0ull;

    auto loadA = [&](int it, float4 &v0, float4 &v1) {
        const float* src = hid + (size_t)(m0 + a_m) * NH + it * 16 + a_k;
        v0 = ((const float4*)src)[0];
        v1 = ((const float4*)src)[1];
    };
    auto loadB = [&](int it, float4 &v0, float4 &v1) {
        const float* src = g_fcT + (size_t)(it * 16 + b_k) * NC + b_q;
        v0 = ((const float4*)src)[0];
        v1 = ((const float4*)src)[1];
    };
    auto stsA = [&](int buf, const float4 &v0, const float4 &v1) {
#pragma unroll
        for (int i = 0; i < 4; i++) {
            float a = (&v0.x)[i];
            *(float2*)&fA[buf][a_k + i][2 * a_m] = make_float2(a, a);
        }
#pragma unroll
        for (int i = 0; i < 4; i++) {
            float a = (&v1.x)[i];
            *(float2*)&fA[buf][a_k + 4 + i][2 * a_m] = make_float2(a, a);
        }
    };
    auto stsB = [&](int buf, const float4 &v0, const float4 &v1) {
        *(float4*)&fB[buf][b_k][b_q]     = v0;
        *(float4*)&fB[buf][b_k][b_q + 4] = v1;
    };

    float4 rA0, rA1, rB0, rB1;
    loadA(0, rA0, rA1); loadB(0, rB0, rB1);
    stsA(0, rA0, rA1); stsB(0, rB0, rB1);
    __syncthreads();

    int cur = 0;
    const int FNITER = NH / 16;
    for (int it = 0; it < FNITER; ++it) {
        const bool more = (it + 1) < FNITER;
        if (more) { loadA(it + 1, rA0, rA1); loadB(it + 1, rB0, rB1); }
#pragma unroll
        for (int kl = 0; kl < 16; ++kl) {
            const ulonglong2 aa0 = *(const ulonglong2*)&fA[cur][kl][8 * ty];
            const ulonglong2 aa1 = *(const ulonglong2*)&fA[cur][kl][8 * ty + 4];
            const ulonglong2 bb0 = *(const ulonglong2*)&fB[cur][kl][c0];
            const ulonglong2 bb1 = *(const ulonglong2*)&fB[cur][kl][c0 + 4];
            fma2(acc[0][0], aa0.x, bb0.x); fma2(acc[0][1], aa0.x, bb0.y);
            fma2(acc[0][2], aa0.x, bb1.x); fma2(acc[0][3], aa0.x, bb1.y);
            fma2(acc[1][0], aa0.y, bb0.x); fma2(acc[1][1], aa0.y, bb0.y);
            fma2(acc[1][2], aa0.y, bb1.x); fma2(acc[1][3], aa0.y, bb1.y);
            fma2(acc[2][0], aa1.x, bb0.x); fma2(acc[2][1], aa1.x, bb0.y);
            fma2(acc[2][2], aa1.x, bb1.x); fma2(acc[2][3], aa1.x, bb1.y);
            fma2(acc[3][0], aa1.y, bb0.x); fma2(acc[3][1], aa1.y, bb0.y);
            fma2(acc[3][2], aa1.y, bb1.x); fma2(acc[3][3], aa1.y, bb1.y);
        }
        if (more) { stsA(cur ^ 1, rA0, rA1); stsB(cur ^ 1, rB0, rB1); }
        __syncthreads();
        cur ^= 1;
    }

    const float4 fb0 = *(const float4*)&fcb[c0];
    const float4 fb1 = *(const float4*)&fcb[c0 + 4];
#pragma unroll
    for (int i = 0; i < 4; i++) {
        const int m = m0 + 4 * ty + i;
        const float2 p0 = u2f(acc[i][0]);
        const float2 p1 = u2f(acc[i][1]);
        const float2 p2 = u2f(acc[i][2]);
        const float2 p3 = u2f(acc[i][3]);
        float4 o0 = make_float4(p0.x + fb0.x, p0.y + fb0.y, p1.x + fb0.z, p1.y + fb0.w);
        float4 o1 = make_float4(p2.x + fb1.x, p2.y + fb1.y, p3.x + fb1.z, p3.y + fb1.w);
        float* dst = out + (size_t)m * NC + c0;
        ((float4*)dst)[0] = o0;
        ((float4*)dst)[1] = o1;
    }
}

// ---------------------------------------------------------------------------
extern "C" void kernel_launch(void* const* d_in, const int* in_sizes, int n_in,
                              void* d_out, int out_size)
{
    const float* x   = (const float*)d_in[0];
    const float* W   = (const float*)d_in[1];
    const float* P   = (const float*)d_in[2];
    const float* b_v = (const float*)d_in[3];
    const float* b_z = (const float*)d_in[4];
    const float* Kw  = (const float*)d_in[5];
    const float* Pz  = (const float*)d_in[6];
    const float* fcw = (const float*)d_in[7];
    const float* fcb = (const float*)d_in[8];

    float* out = (float*)d_out;
    float* hid = out + (size_t)NB * NT * NC;

    (void)in_sizes; (void)n_in; (void)out_size;

    static int smem_set = 0;
    if (!smem_set) {
        cudaFuncSetAttribute(scan_kernel,
                             cudaFuncAttributeMaxDynamicSharedMemorySize, SMEM_BYTES);
        smem_set = 1;
    }

    prep_kernel<<<(576 * 1024 + NH * NC + 255) / 256, 256>>>(W, P, Kw, Pz, fcw);
    prep_xdup<<<dim3(NT, NB / 32), 256>>>(x);

    dim3 sgrid(32, 4);   // 128 CTAs — one wave, persistent
    scan_kernel<<<sgrid, TPB, SMEM_BYTES>>>(b_z, b_v, hid);

    fc_kernel<<<(NB * NT) / FBM, 128>>>(hid, fcb, out);
}

// round 15
// speedup vs baseline: 1.5761x; 1.3609x over previous
#include <cuda_runtime.h>
#include <math.h>
#include <stdint.h>

// Problem dims
#define NB 256
#define NT 512
#define ND 64
#define NH 512
#define NC 64
#define DTF 0.1f

// Scan config: grid (32 h-tiles, 4 m-tiles) = 128 CTAs, 256 threads (2 teams x 128)
#define TPB 256
#define BM 64
#define BK 32
#define NSTG 4
// smem: B [576][32] | A stages 2 teams x 4 x [32][128] | sred 128x8 u64
#define SMEM_B_FLOATS   (576 * 32)
#define SMEM_A_FLOATS   (2 * NSTG * BK * 128)
#define SMEM_RED_BYTES  (128 * 8 * 8)
#define SMEM_BYTES      ((SMEM_B_FLOATS + SMEM_A_FLOATS) * 4 + SMEM_RED_BYTES) // 212992

// FC tiling
#define FBM 64

// Static scratch
__device__ float g_B[576 * 1024];             // [k][n], n=(h/2)*4+{z0,z1,v0,v1}
__device__ float g_xdup[NT * ND * 2 * NB];    // [t][d][2m]
__device__ float g_rdup[2 * NH * 2 * NB];     // [slot][h][2m]
__device__ float g_fcT[NH * NC];
__device__ unsigned int g_barv[128];          // 4 group counters, 128B apart

// ---------------------------------------------------------------------------
__device__ __forceinline__ void fma2(unsigned long long &d,
                                     unsigned long long a,
                                     unsigned long long b) {
    asm("fma.rn.f32x2 %0, %1, %2, %0;" : "+l"(d) : "l"(a), "l"(b));
}
__device__ __forceinline__ unsigned long long add2(unsigned long long a,
                                                   unsigned long long b) {
    unsigned long long r;
    asm("add.rn.f32x2 %0, %1, %2;" : "=l"(r) : "l"(a), "l"(b));
    return r;
}
__device__ __forceinline__ float2 u2f(unsigned long long u) {
    float2 r;
    asm("mov.b64 {%0, %1}, %2;" : "=f"(r.x), "=f"(r.y) : "l"(u));
    return r;
}
__device__ __forceinline__ void cp16(uint32_t dst, const void* src) {
    asm volatile("cp.async.cg.shared.global [%0], [%1], 16;" :: "r"(dst), "l"(src));
}
#define CP_COMMIT() asm volatile("cp.async.commit_group;")
#define BAR_TEAM(id) asm volatile("bar.sync %0, 128;" :: "r"(id) : "memory")

// ---------------------------------------------------------------------------
__global__ void prep_kernel(const float* __restrict__ W,  const float* __restrict__ P,
                            const float* __restrict__ Kw, const float* __restrict__ Pz,
                            const float* __restrict__ fcw) {
    int idx = blockIdx.x * blockDim.x + threadIdx.x;
    if (idx < 128) g_barv[idx] = 0u;
    const int totalB = 576 * 1024;
    if (idx < totalB) {
        int k = idx >> 10;
        int n = idx & 1023;
        int h = ((n >> 2) << 1) | (n & 1);
        bool isv = (n & 2) != 0;
        float val;
        if (k < NH) {
            val = isv ? W[h * NH + k] : Kw[h * NH + k];
        } else {
            int d = k - NH;
            val = isv ? ((h < NH / 2) ? P[h * ND + d] : 0.0f)
                      : Pz[h * ND + d];
        }
        g_B[idx] = val;
    } else {
        int j = idx - totalB;
        if (j < NH * NC) {
            int k = j >> 6;
            int c = j & 63;
            g_fcT[j] = fcw[c * NH + k];
        }
    }
}

__global__ void __launch_bounds__(256)
prep_xdup(const float* __restrict__ x) {
    __shared__ float s[64][33];
    const int t  = blockIdx.x;
    const int m0 = blockIdx.y * 32;
    const int tid = threadIdx.x;
#pragma unroll
    for (int i = 0; i < 8; i++) {
        int idx = tid + i * 256;
        int ml = idx >> 6, d = idx & 63;
        s[d][ml] = x[((size_t)(m0 + ml) * NT + t) * ND + d];
    }
    __syncthreads();
#pragma unroll
    for (int i = 0; i < 8; i++) {
        int idx = tid + i * 256;
        int d = idx >> 5, ml = idx & 31;
        float v = s[d][ml];
        *(float2*)&g_xdup[((size_t)t * ND + d) * 512 + 2 * (m0 + ml)] = make_float2(v, v);
    }
}

// ---------------------------------------------------------------------------
// Persistent scan (R12 base): group barrier per m-group, 2 k-split teams,
// 4-stage / depth-3 cp.async pipeline for recurrent chunks.
// ---------------------------------------------------------------------------
__global__ void __launch_bounds__(TPB)
scan_kernel(const float* __restrict__ bz_g,
            const float* __restrict__ bv_g,
            float* __restrict__ hid)
{
    extern __shared__ float smem[];
    float* sBf = smem;                                   // [576][32]
    float* sA  = smem + SMEM_B_FLOATS;                   // 2 teams x 4 x [32][128]
    unsigned long long* sred =
        (unsigned long long*)(smem + SMEM_B_FLOATS + SMEM_A_FLOATS); // [128][8]

    const int tid  = threadIdx.x;
    const int team = tid >> 7;          // 0 or 1
    const int ttid = tid & 127;
    const int bx   = blockIdx.x;        // h-tile 0..31
    const int by   = blockIdx.y;        // m-tile 0..3
    const int m0   = by * BM;
    const int tx   = ttid & 7;          // h-pair 0..7
    const int ty   = ttid >> 3;         // m-quad 0..15

    unsigned int* ctr = &g_barv[by * 32];

    // ---- load B slice once ----
#pragma unroll
    for (int r = 0; r < 18; r++) {
        int i = tid + r * TPB;
        int row = i >> 3, c = (i & 7) << 2;
        uint32_t dst = (uint32_t)__cvta_generic_to_shared(&sBf[row * 32 + c]);
        cp16(dst, g_B + (size_t)row * 1024 + bx * 32 + c);
    }
    CP_COMMIT();
    asm volatile("cp.async.wait_group 0;");
    __syncthreads();

    const int h2 = bx * 8 + tx;
    const int hg = h2 * 2;
    const float2 bz = *(const float2*)&bz_g[hg];
    const float2 bv = *(const float2*)&bv_g[hg];

    float* sAteam = sA + team * (NSTG * BK * 128);
    const int barid = 1 + team;

    // v-state (team 0 threads own it): 4 m x (h0,h1)
    float2 vs0 = {0,0}, vs1 = {0,0}, vs2 = {0,0}, vs3 = {0,0};

    auto issueChunk = [&](int stg, const float* gbase) {
#pragma unroll
        for (int r = 0; r < 8; r++) {
            int id = ttid + r * 128;
            int kk = id >> 5, c = (id & 31) << 2;
            uint32_t dst = (uint32_t)__cvta_generic_to_shared(
                &sAteam[(stg * BK + kk) * 128 + c]);
            cp16(dst, gbase + (size_t)kk * 512 + c);
        }
        CP_COMMIT();
    };

    unsigned long long az0, az1, az2, az3, av0, av1, av2, av3;

    auto computeChunk = [&](int stg, int kbase) {
        const float* pa = sAteam + (stg * BK) * 128 + ty * 8;
        const float* pb = sBf + kbase * 32 + tx * 4;
        ulonglong2 a0 = *(const ulonglong2*)(pa);
        ulonglong2 a1 = *(const ulonglong2*)(pa + 4);
        ulonglong2 b  = *(const ulonglong2*)(pb);
#pragma unroll
        for (int kk = 0; kk < BK; ++kk) {
            ulonglong2 na0, na1, nb;
            if (kk < BK - 1) {
                na0 = *(const ulonglong2*)(pa + (kk + 1) * 128);
                na1 = *(const ulonglong2*)(pa + (kk + 1) * 128 + 4);
                nb  = *(const ulonglong2*)(pb + (kk + 1) * 32);
            }
            fma2(az0, a0.x, b.x); fma2(av0, a0.x, b.y);
            fma2(az1, a0.y, b.x); fma2(av1, a0.y, b.y);
            fma2(az2, a1.x, b.x); fma2(av2, a1.x, b.y);
            fma2(az3, a1.y, b.x); fma2(av3, a1.y, b.y);
            if (kk < BK - 1) { a0 = na0; a1 = na1; b = nb; }
        }
    };

    // chunk 0 = x (d in [32*team, 32*team+32)); chunks 1..8 = recurrent
    const size_t xoff = (size_t)32 * team * 512 + 2 * m0;
    const size_t roff = (size_t)256 * team * 512 + 2 * m0;
    const int kb_x = 512 + 32 * team;
    const int kb_r = 256 * team;

    // prologue: x chunk for t=0 into stage 0
    issueChunk(0, g_xdup + xoff);

#pragma unroll 1
    for (int t = 0; t < NT; ++t) {
        az0 = az1 = az2 = az3 = 0ull;
        av0 = av1 = av2 = av3 = 0ull;

        // x chunk is the only outstanding group at loop top
        asm volatile("cp.async.wait_group 0;");

        // group barrier: all 32 CTAs of this m-group past step t-1
        if (tid == 0 && t > 0) {
            unsigned int target = (unsigned int)(32 * t);
            unsigned int v;
            do {
                asm volatile("ld.acquire.gpu.global.u32 %0, [%1];"
                             : "=r"(v) : "l"(ctr));
            } while (v < target);
        }
        __syncthreads();   // broadcasts poll + makes x stage readable

        if (t == 0) {
            computeChunk(0, kb_x);
        } else {
            const float* rbase = g_rdup + (size_t)((t + 1) & 1) * (NH * 512) + roff;
            // depth-3 prefetch: chunks 1,2,3 in flight before computing x
            issueChunk(1, rbase);
            issueChunk(2, rbase + (size_t)BK * 512);
            issueChunk(3, rbase + (size_t)2 * BK * 512);
            computeChunk(0, kb_x);
#pragma unroll 1
            for (int c = 1; c <= 8; ++c) {
                if (c <= 6)      { asm volatile("cp.async.wait_group 2;"); }
                else if (c == 7) { asm volatile("cp.async.wait_group 1;"); }
                else             { asm volatile("cp.async.wait_group 0;"); }
                BAR_TEAM(barid);
                if (c + 3 <= 8)
                    issueChunk((c + 3) & 3, rbase + (size_t)(c + 2) * BK * 512);
                computeChunk(c & 3, kb_r + (c - 1) * BK);
            }
        }

        // prefetch x chunk for t+1 into stage 0 (overlaps reduction/epilogue)
        if (t + 1 < NT)
            issueChunk(0, g_xdup + (size_t)(t + 1) * (ND * 512) + xoff);

        // ---- cross-team reduction ----
        if (team == 1) {
            unsigned long long* d = &sred[ttid * 8];
            *(ulonglong2*)(d)     = make_ulonglong2(az0, av0);
            *(ulonglong2*)(d + 2) = make_ulonglong2(az1, av1);
            *(ulonglong2*)(d + 4) = make_ulonglong2(az2, av2);
            *(ulonglong2*)(d + 6) = make_ulonglong2(az3, av3);
        }
        __syncthreads();

        if (team == 0) {
            const unsigned long long* d = &sred[ttid * 8];
            ulonglong2 q0 = *(const ulonglong2*)(d);
            ulonglong2 q1 = *(const ulonglong2*)(d + 2);
            ulonglong2 q2 = *(const ulonglong2*)(d + 4);
            ulonglong2 q3 = *(const ulonglong2*)(d + 6);
            az0 = add2(az0, q0.x); av0 = add2(av0, q0.y);
            az1 = add2(az1, q1.x); av1 = add2(av1, q1.y);
            az2 = add2(az2, q2.x); av2 = add2(av2, q2.y);
            az3 = add2(az3, q3.x); av3 = add2(av3, q3.y);

            const int mA = m0 + 4 * ty;
            float2 z, v;

            z = u2f(az0); v = u2f(av0);
            {
                float s0 = 1.0f / (1.0f + __expf(-(z.x + bz.x)));
                float s1 = 1.0f / (1.0f + __expf(-(z.y + bz.y)));
                vs0.x = (1.0f - s0) * vs0.x + DTF * (v.x + bv.x);
                vs0.y = (1.0f - s1) * vs0.y + DTF * (v.y + bv.y);
            }
            z = u2f(az1); v = u2f(av1);
            {
                float s0 = 1.0f / (1.0f + __expf(-(z.x + bz.x)));
                float s1 = 1.0f / (1.0f + __expf(-(z.y + bz.y)));
                vs1.x = (1.0f - s0) * vs1.x + DTF * (v.x + bv.x);
                vs1.y = (1.0f - s1) * vs1.y + DTF * (v.y + bv.y);
            }
            z = u2f(az2); v = u2f(av2);
            {
                float s0 = 1.0f / (1.0f + __expf(-(z.x + bz.x)));
                float s1 = 1.0f / (1.0f + __expf(-(z.y + bz.y)));
                vs2.x = (1.0f - s0) * vs2.x + DTF * (v.x + bv.x);
                vs2.y = (1.0f - s1) * vs2.y + DTF * (v.y + bv.y);
            }
            z = u2f(az3); v = u2f(av3);
            {
                float s0 = 1.0f / (1.0f + __expf(-(z.x + bz.x)));
                float s1 = 1.0f / (1.0f + __expf(-(z.y + bz.y)));
                vs3.x = (1.0f - s0) * vs3.x + DTF * (v.x + bv.x);
                vs3.y = (1.0f - s1) * vs3.y + DTF * (v.y + bv.y);
            }

            *(float2*)&hid[((size_t)(mA + 0) * NT + t) * NH + hg] = vs0;
            *(float2*)&hid[((size_t)(mA + 1) * NT + t) * NH + hg] = vs1;
            *(float2*)&hid[((size_t)(mA + 2) * NT + t) * NH + hg] = vs2;
            *(float2*)&hid[((size_t)(mA + 3) * NT + t) * NH + hg] = vs3;

            const float r0x = fmaxf(vs0.x, 0.0f), r0y = fmaxf(vs0.y, 0.0f);
            const float r1x = fmaxf(vs1.x, 0.0f), r1y = fmaxf(vs1.y, 0.0f);
            const float r2x = fmaxf(vs2.x, 0.0f), r2y = fmaxf(vs2.y, 0.0f);
            const float r3x = fmaxf(vs3.x, 0.0f), r3y = fmaxf(vs3.y, 0.0f);

            float* rd = g_rdup + (size_t)(t & 1) * (NH * 512);
            float* sp0 = &rd[(size_t)hg * 512 + 2 * mA];
            ((float4*)sp0)[0] = make_float4(r0x, r0x, r1x, r1x);
            ((float4*)sp0)[1] = make_float4(r2x, r2x, r3x, r3x);
            float* sp1 = &rd[(size_t)(hg + 1) * 512 + 2 * mA];
            ((float4*)sp1)[0] = make_float4(r0y, r0y, r1y, r1y);
            ((float4*)sp1)[1] = make_float4(r2y, r2y, r3y, r3y);

            BAR_TEAM(barid);
            if (tid == 0) {
                __threadfence();
                asm volatile("red.release.gpu.global.add.u32 [%0], %1;"
                             :: "l"(ctr), "r"(1u) : "memory");
            }
        }
    }
}

// ---------------------------------------------------------------------------
// FC (unchanged)
// ---------------------------------------------------------------------------
__global__ void __launch_bounds__(128)
fc_kernel(const float* __restrict__ hid,
          const float* __restrict__ fcb,
          float* __restrict__ out)
{
    __shared__ __align__(16) float fA[2][16][2 * FBM];
    __shared__ __align__(16) float fB[2][16][NC];

    const int tid = threadIdx.x;
    const int m0 = blockIdx.x * FBM;
    const int tx = tid & 7;
    const int ty = tid >> 3;
    const int c0 = tx * 8;

    const int a_m = tid >> 1;
    const int a_k = (tid & 1) * 8;
    const int b_k = tid >> 3;
    const int b_q = (tid & 7) * 8;

    unsigned long long acc[4][4];
#pragma unroll
    for (int i = 0; i < 4; i++)
#pragma unroll
        for (int j = 0; j < 4; j++) acc[i][j] = 0ull;

    auto loadA = [&](int it, float4 &v0, float4 &v1) {
        const float* src = hid + (size_t)(m0 + a_m) * NH + it * 16 + a_k;
        v0 = ((const float4*)src)[0];
        v1 = ((const float4*)src)[1];
    };
    auto loadB = [&](int it, float4 &v0, float4 &v1) {
        const float* src = g_fcT + (size_t)(it * 16 + b_k) * NC + b_q;
        v0 = ((const float4*)src)[0];
        v1 = ((const float4*)src)[1];
    };
    auto stsA = [&](int buf, const float4 &v0, const float4 &v1) {
#pragma unroll
        for (int i = 0; i < 4; i++) {
            float a = (&v0.x)[i];
            *(float2*)&fA[buf][a_k + i][2 * a_m] = make_float2(a, a);
        }
#pragma unroll
        for (int i = 0; i < 4; i++) {
            float a = (&v1.x)[i];
            *(float2*)&fA[buf][a_k + 4 + i][2 * a_m] = make_float2(a, a);
        }
    };
    auto stsB = [&](int buf, const float4 &v0, const float4 &v1) {
        *(float4*)&fB[buf][b_k][b_q]     = v0;
        *(float4*)&fB[buf][b_k][b_q + 4] = v1;
    };

    float4 rA0, rA1, rB0, rB1;
    loadA(0, rA0, rA1); loadB(0, rB0, rB1);
    stsA(0, rA0, rA1); stsB(0, rB0, rB1);
    __syncthreads();

    int cur = 0;
    const int FNITER = NH / 16;
    for (int it = 0; it < FNITER; ++it) {
        const bool more = (it + 1) < FNITER;
        if (more) { loadA(it + 1, rA0, rA1); loadB(it + 1, rB0, rB1); }
#pragma unroll
        for (int kl = 0; kl < 16; ++kl) {
            const ulonglong2 aa0 = *(const ulonglong2*)&fA[cur][kl][8 * ty];
            const ulonglong2 aa1 = *(const ulonglong2*)&fA[cur][kl][8 * ty + 4];
            const ulonglong2 bb0 = *(const ulonglong2*)&fB[cur][kl][c0];
            const ulonglong2 bb1 = *(const ulonglong2*)&fB[cur][kl][c0 + 4];
            fma2(acc[0][0], aa0.x, bb0.x); fma2(acc[0][1], aa0.x, bb0.y);
            fma2(acc[0][2], aa0.x, bb1.x); fma2(acc[0][3], aa0.x, bb1.y);
            fma2(acc[1][0], aa0.y, bb0.x); fma2(acc[1][1], aa0.y, bb0.y);
            fma2(acc[1][2], aa0.y, bb1.x); fma2(acc[1][3], aa0.y, bb1.y);
            fma2(acc[2][0], aa1.x, bb0.x); fma2(acc[2][1], aa1.x, bb0.y);
            fma2(acc[2][2], aa1.x, bb1.x); fma2(acc[2][3], aa1.x, bb1.y);
            fma2(acc[3][0], aa1.y, bb0.x); fma2(acc[3][1], aa1.y, bb0.y);
            fma2(acc[3][2], aa1.y, bb1.x); fma2(acc[3][3], aa1.y, bb1.y);
        }
        if (more) { stsA(cur ^ 1, rA0, rA1); stsB(cur ^ 1, rB0, rB1); }
        __syncthreads();
        cur ^= 1;
    }

    const float4 fb0 = *(const float4*)&fcb[c0];
    const float4 fb1 = *(const float4*)&fcb[c0 + 4];
#pragma unroll
    for (int i = 0; i < 4; i++) {
        const int m = m0 + 4 * ty + i;
        const float2 p0 = u2f(acc[i][0]);
        const float2 p1 = u2f(acc[i][1]);
        const float2 p2 = u2f(acc[i][2]);
        const float2 p3 = u2f(acc[i][3]);
        float4 o0 = make_float4(p0.x + fb0.x, p0.y + fb0.y, p1.x + fb0.z, p1.y + fb0.w);
        float4 o1 = make_float4(p2.x + fb1.x, p2.y + fb1.y, p3.x + fb1.z, p3.y + fb1.w);
        float* dst = out + (size_t)m * NC + c0;
        ((float4*)dst)[0] = o0;
        ((float4*)dst)[1] = o1;
    }
}

// ---------------------------------------------------------------------------
extern "C" void kernel_launch(void* const* d_in, const int* in_sizes, int n_in,
                              void* d_out, int out_size)
{
    const float* x   = (const float*)d_in[0];
    const float* W   = (const float*)d_in[1];
    const float* P   = (const float*)d_in[2];
    const float* b_v = (const float*)d_in[3];
    const float* b_z = (const float*)d_in[4];
    const float* Kw  = (const float*)d_in[5];
    const float* Pz  = (const float*)d_in[6];
    const float* fcw = (const float*)d_in[7];
    const float* fcb = (const float*)d_in[8];

    float* out = (float*)d_out;
    float* hid = out + (size_t)NB * NT * NC;

    (void)in_sizes; (void)n_in; (void)out_size;

    static int smem_set = 0;
    if (!smem_set) {
        cudaFuncSetAttribute(scan_kernel,
                             cudaFuncAttributeMaxDynamicSharedMemorySize, SMEM_BYTES);
        smem_set = 1;
    }

    prep_kernel<<<(576 * 1024 + NH * NC + 255) / 256, 256>>>(W, P, Kw, Pz, fcw);
    prep_xdup<<<dim3(NT, NB / 32), 256>>>(x);

    dim3 sgrid(32, 4);   // 128 CTAs — one wave, persistent
    scan_kernel<<<sgrid, TPB, SMEM_BYTES>>>(b_z, b_v, hid);

    fc_kernel<<<(NB * NT) / FBM, 128>>>(hid, fcb, out);
}